// round 7
// baseline (speedup 1.0000x reference)
#include <cuda_runtime.h>
#include <cstdint>

#define BATCH   2048
#define TT      50
#define NNODES  23
#define FF      4
#define HH      64
#define FUT     10
#define BPC     2                 // batches per CTA
#define ROWS    (BPC*NNODES)      // 46
#define MPAD    48
#define THREADS 512
#define CS      196               // sC row stride: 64 spa | 64 hA | 64 hB | 4 pad
#define SS      68                // sSup row stride

// smem floats
#define SZ_RZ   (128*128)         // packed r/z weights [k][4p+q]
#define SZ_N    (128*64)          // n weights [k][j]
#define SZ_C    (MPAD*CS)
#define SMEM_FLOATS (SZ_RZ+SZ_N+SZ_C+3264+1104+184+256+64+128+64+64+2048+32+128+4)

typedef unsigned long long u64;

__device__ __forceinline__ void fma2(u64& d, u64 a, u64 b) {
    asm("fma.rn.f32x2 %0, %1, %2, %0;" : "+l"(d) : "l"(a), "l"(b));
}
__device__ __forceinline__ float2 unpk(u64 v) {
    float2 r; asm("mov.b64 {%0, %1}, %2;" : "=f"(r.x), "=f"(r.y) : "l"(v)); return r;
}
__device__ __forceinline__ u64 dup2(float a) {
    u64 r; asm("mov.b64 %0, {%1, %1};" : "=l"(r) : "f"(a)); return r;
}
__device__ __forceinline__ float sigmoidf_(float x) {
    return __fdividef(1.f, 1.f + __expf(-x));
}
__device__ __forceinline__ float tanhf_(float x) {
    return __fdividef(2.f, 1.f + __expf(-2.f * x)) - 1.f;
}

// 16 kb-quads of the gate GEMM; A from sC+aoff (3 rows), B rows kbase+..
// aR/aZ accumulate r,z; aN accumulates n for this half only.
__device__ __forceinline__ void gemm_q(const float* __restrict__ sC,
                                       const float* __restrict__ sRZ,
                                       const float* __restrict__ sN,
                                       int m0, int p, int jr,
                                       int aoff, int kbase,
                                       u64 aR[3], u64 aZ[3], u64 aN[3]) {
#pragma unroll 2
    for (int kb = 0; kb < 16; ++kb) {
        float4 a0 = *(const float4*)(sC + (m0+0)*CS + aoff + kb*4);
        float4 a1 = *(const float4*)(sC + (m0+1)*CS + aoff + kb*4);
        float4 a2 = *(const float4*)(sC + (m0+2)*CS + aoff + kb*4);
#pragma unroll
        for (int kk = 0; kk < 4; ++kk) {
            const int k = kbase + kb*4 + kk;
            ulonglong2 brz = *(const ulonglong2*)(sRZ + k*128 + p*4);
            u64        bn  = *(const u64*)(sN + k*64 + jr);
            float f0 = kk==0 ? a0.x : kk==1 ? a0.y : kk==2 ? a0.z : a0.w;
            float f1 = kk==0 ? a1.x : kk==1 ? a1.y : kk==2 ? a1.z : a1.w;
            float f2 = kk==0 ? a2.x : kk==1 ? a2.y : kk==2 ? a2.z : a2.w;
            u64 d0 = dup2(f0), d1 = dup2(f1), d2 = dup2(f2);
            fma2(aR[0], d0, brz.x); fma2(aZ[0], d0, brz.y); fma2(aN[0], d0, bn);
            fma2(aR[1], d1, brz.x); fma2(aZ[1], d1, brz.y); fma2(aN[1], d1, bn);
            fma2(aR[2], d2, brz.x); fma2(aZ[2], d2, brz.y); fma2(aN[2], d2, bn);
        }
    }
}

extern "C" __global__ void __launch_bounds__(THREADS, 1)
gwm_kernel(const float* __restrict__ x_seq, const float* __restrict__ adj_seq,
           const float* __restrict__ W_gcn, const float* __restrict__ b_gcn,
           const float* __restrict__ W_ih,  const float* __restrict__ W_hh,
           const float* __restrict__ b_ih,  const float* __restrict__ b_hh,
           const float* __restrict__ W_d1,  const float* __restrict__ b_d1,
           const float* __restrict__ W_d2,  const float* __restrict__ b_d2,
           float* __restrict__ out)
{
    extern __shared__ float sm[];
    float* sRZ  = sm;                 // [k=0..127][4p+q]  k<64: W_ih^T, k>=64: W_hh^T
    float* sN   = sRZ  + SZ_RZ;       // [k][j] n-gate
    float* sC   = sN   + SZ_N;        // [48][196]: 0..63 spa | 64..127 hA | 128..191 hB
    float* sSup = sC   + SZ_C;        // [48][68]
    float* sAdj = sSup + 3264;        // [r][24]
    float* sX   = sAdj + 1104;        // [r][4]
    float* sWg  = sX   + 184;         // [j][4]
    float* sbg  = sWg  + 256;
    float* sbrz = sbg  + 64;          // b_ih+b_hh, j 0..127 (r,z)
    float* sbin = sbrz + 128;         // b_ih[128+j]
    float* sbhn = sbin + 64;          // b_hh[128+j]
    float* sWd1 = sbhn + 64;          // [q][64]
    float* sbd1 = sWd1 + 2048;
    float* sWd2 = sbd1 + 32;          // [f][32]
    float* sbd2 = sWd2 + 128;

    const int tid  = threadIdx.x;
    const int w    = tid >> 5;
    const int lane = tid & 31;
    const int b0   = blockIdx.x * BPC;

    // GEMM tile mapping
    const int wm = w >> 3;            // 0..1
    const int wn = w & 7;             // 0..7
    const int ml = lane & 7;          // 0..7
    const int ng = lane >> 3;         // 0..3
    const int m0 = wm*24 + ml*3;      // rows m0..m0+2
    const int p  = wn*4 + ng;         // j-pair index 0..31
    const int jr = p*2;               // even j 0..62

    // ---- one-time setup ----
    for (int e = tid; e < 128*64; e += THREADS) {
        int k = e >> 6, j = e & 63;
        float wr, wz, wnv;
        if (k < 64) {
            wr  = W_ih[j*64 + k];
            wz  = W_ih[(64+j)*64 + k];
            wnv = W_ih[(128+j)*64 + k];
        } else {
            wr  = W_hh[j*64 + (k-64)];
            wz  = W_hh[(64+j)*64 + (k-64)];
            wnv = W_hh[(128+j)*64 + (k-64)];
        }
        int pp = j >> 1, q = j & 1;
        sRZ[k*128 + pp*4 + q]     = wr;
        sRZ[k*128 + pp*4 + 2 + q] = wz;
        sN [k*64 + j]             = wnv;
    }
    for (int e = tid; e < 256;  e += THREADS) sWg[e]  = W_gcn[e];
    for (int e = tid; e < 2048; e += THREADS) sWd1[e] = W_d1[e];
    if (tid < 64)  sbg[tid]  = b_gcn[tid];
    if (tid < 128) sbrz[tid] = b_ih[tid] + b_hh[tid];
    if (tid >= 128 && tid < 192) sbin[tid-128] = b_ih[tid];
    if (tid >= 192 && tid < 256) sbhn[tid-192] = b_hh[tid-64];   // b_hh[128..191]
    if (tid < 32)  sbd1[tid] = b_d1[tid];
    if (tid < 128) sWd2[tid] = W_d2[tid];
    if (tid < 4)   sbd2[tid] = b_d2[tid];
    for (int e = tid; e < MPAD*CS; e += THREADS) sC[e] = 0.f;   // spa=0, hA=hB=0
    __syncthreads();

    for (int t = 0; t < TT + FUT; ++t) {
        const bool hist = (t < TT);
        const int  hoff  = 64 + 64*(t & 1);        // h_t buffer
        const int  hoff2 = 64 + 64*((t+1) & 1);    // h_{t+1} buffer
        if (hist) {
            for (int e = tid; e < BPC*NNODES*NNODES; e += THREADS) {
                int bl = e / (NNODES*NNODES);
                int i  = e - bl*(NNODES*NNODES);
                int n  = i / NNODES, m = i - n*NNODES;
                sAdj[(bl*NNODES + n)*24 + m] =
                    adj_seq[((size_t)(b0+bl)*TT + t)*(NNODES*NNODES) + i];
            }
            for (int e = tid; e < ROWS*FF; e += THREADS) {
                int bl = e / (NNODES*FF);
                int i  = e - bl*(NNODES*FF);
                sX[e] = x_seq[((size_t)(b0+bl)*TT + t)*(NNODES*FF) + i];
            }
            __syncthreads();
        }

        // ---- phase 1: support = x @ Wg^T + bg ----
        for (int e = tid; e < ROWS*HH; e += THREADS) {
            int r = e >> 6, j = e & 63;
            const float* xp = sX + r*FF;
            float v = sbg[j];
            v = fmaf(xp[0], sWg[j*4+0], v);
            v = fmaf(xp[1], sWg[j*4+1], v);
            v = fmaf(xp[2], sWg[j*4+2], v);
            v = fmaf(xp[3], sWg[j*4+3], v);
            sSup[r*SS + j] = v;
        }
        __syncthreads();

        // ---- phase 2: spa = relu(adj @ support) -> sC[:, 0..63] ----
        {
            const int rh = lane >> 4, jq = lane & 15;
            for (int pp = w; pp < 23; pp += 16) {
                int r  = 2*pp + rh;                   // 0..45
                int bl = r / NNODES;
                const float* arow = sAdj + r*24;
                const float* supb = sSup + (bl*NNODES)*SS;
                u64 a0 = 0ull, a1 = 0ull;
#pragma unroll
                for (int m = 0; m < NNODES; ++m) {
                    u64 am = dup2(arow[m]);
                    ulonglong2 s = *(const ulonglong2*)(supb + m*SS + 4*jq);
                    fma2(a0, am, s.x);
                    fma2(a1, am, s.y);
                }
                float2 f0 = unpk(a0), f1 = unpk(a1);
                float4 o;
                o.x = fmaxf(f0.x, 0.f); o.y = fmaxf(f0.y, 0.f);
                o.z = fmaxf(f1.x, 0.f); o.w = fmaxf(f1.y, 0.f);
                *(float4*)(sC + r*CS + 4*jq) = o;
            }
        }
        __syncthreads();

        // ---- phase 3: gate GEMM, one K=128 sweep ----
        u64 aR[3], aZ[3], aNlo[3], aNhi[3];
#pragma unroll
        for (int mi = 0; mi < 3; ++mi) { aR[mi]=0ull; aZ[mi]=0ull; aNlo[mi]=0ull; aNhi[mi]=0ull; }

        gemm_q(sC, sRZ, sN, m0, p, jr, 0,    0,  aR, aZ, aNlo);  // spa @ W_ih^T
        gemm_q(sC, sRZ, sN, m0, p, jr, hoff, 64, aR, aZ, aNhi);  // h   @ W_hh^T

        // ---- GRU epilogue (in registers) ----
        {
            const float2 br_ = *(const float2*)(sbrz + jr);
            const float2 bz_ = *(const float2*)(sbrz + 64 + jr);
            const float2 bi_ = *(const float2*)(sbin + jr);
            const float2 bh_ = *(const float2*)(sbhn + jr);
#pragma unroll
            for (int mi = 0; mi < 3; ++mi) {
                float2 rv = unpk(aR[mi]);
                float2 zv = unpk(aZ[mi]);
                float2 nI = unpk(aNlo[mi]);
                float2 nH = unpk(aNhi[mi]);
                float r0 = sigmoidf_(rv.x + br_.x);
                float r1 = sigmoidf_(rv.y + br_.y);
                float z0 = sigmoidf_(zv.x + bz_.x);
                float z1 = sigmoidf_(zv.y + bz_.y);
                float n0 = tanhf_(nI.x + bi_.x + r0*(nH.x + bh_.x));
                float n1 = tanhf_(nI.y + bi_.y + r1*(nH.y + bh_.y));
                float2 ho = *(const float2*)(sC + (m0+mi)*CS + hoff + jr);
                // write h_{t+1} into the OTHER buffer: no one reads it this step
                *(float2*)(sC + (m0+mi)*CS + hoff2 + jr) =
                    make_float2((1.f - z0)*n0 + z0*ho.x, (1.f - z1)*n1 + z1*ho.y);
            }
        }
        __syncthreads();   // h_{t+1} visible; all reads of spa/h_t done

        // ---- decode (future steps only) ----
        if (!hist) {
            const int s = t - TT;
            if (w < 8) {
                const int q0 = w * 4;
#pragma unroll
                for (int rg = 0; rg < 2; ++rg) {
                    int r  = rg*32 + lane;
                    int rr = (r < ROWS) ? r : 0;
                    const float* hp = sC + rr*CS + hoff2;
                    float acc[4] = {0.f,0.f,0.f,0.f};
#pragma unroll 4
                    for (int kq = 0; kq < 16; ++kq) {
                        float4 hh = *(const float4*)(hp + kq*4);
#pragma unroll
                        for (int jj = 0; jj < 4; ++jj) {
                            const float4 wd = *(const float4*)(sWd1 + (q0+jj)*64 + kq*4);
                            float a = acc[jj];
                            a = fmaf(hh.x, wd.x, a); a = fmaf(hh.y, wd.y, a);
                            a = fmaf(hh.z, wd.z, a); a = fmaf(hh.w, wd.w, a);
                            acc[jj] = a;
                        }
                    }
                    if (r < ROWS) {
#pragma unroll
                        for (int jj = 0; jj < 4; ++jj)
                            sSup[r*SS + q0 + jj] = fmaxf(acc[jj] + sbd1[q0+jj], 0.f);
                    }
                }
            }
            __syncthreads();
            for (int e = tid; e < ROWS*FF; e += THREADS) {
                int r = e >> 2, f = e & 3;
                float v = sbd2[f];
#pragma unroll
                for (int q = 0; q < 32; ++q)
                    v = fmaf(sSup[r*SS + q], sWd2[f*32 + q], v);
                sX[e] = v;
                int bl = r / NNODES, n = r - bl*NNODES;
                out[(((size_t)(b0+bl)*FUT + s)*NNODES + n)*FF + f] = v;
            }
            __syncthreads();
        }
    }
}

extern "C" void kernel_launch(void* const* d_in, const int* in_sizes, int n_in,
                              void* d_out, int out_size) {
    const float* x_seq  = (const float*)d_in[0];
    const float* adj    = (const float*)d_in[1];
    const float* W_gcn  = (const float*)d_in[2];
    const float* b_gcn  = (const float*)d_in[3];
    const float* W_ih   = (const float*)d_in[4];
    const float* W_hh   = (const float*)d_in[5];
    const float* b_ih   = (const float*)d_in[6];
    const float* b_hh   = (const float*)d_in[7];
    const float* W_d1   = (const float*)d_in[8];
    const float* b_d1   = (const float*)d_in[9];
    const float* W_d2   = (const float*)d_in[10];
    const float* b_d2   = (const float*)d_in[11];
    float* out = (float*)d_out;

    const int smem_bytes = SMEM_FLOATS * (int)sizeof(float);
    cudaFuncSetAttribute(gwm_kernel, cudaFuncAttributeMaxDynamicSharedMemorySize, smem_bytes);
    gwm_kernel<<<BATCH / BPC, THREADS, smem_bytes>>>(
        x_seq, adj, W_gcn, b_gcn, W_ih, W_hh, b_ih, b_hh,
        W_d1, b_d1, W_d2, b_d2, out);
}